// round 8
// baseline (speedup 1.0000x reference)
#include <cuda_runtime.h>
#include <math.h>

// ---------------------------------------------------------------------------
// Problem constants
// ---------------------------------------------------------------------------
#define T_LEN 512
#define B_SZ  64
#define HID   512
#define G4    2048          // 4*HID (gate rows)
#define CTXD  792
#define INDIM 1048
#define NCTA  256           // persistent recurrence CTAs (2 units each, 2/SM)

// ---------------------------------------------------------------------------
// Device scratch
// ---------------------------------------------------------------------------
__device__ float d_gctx[B_SZ * G4];                               // [b][g]
__device__ float d_P[260 * 8 * G4];                               // [(v*8+j)][g]
__device__ float d_gx0[(size_t)T_LEN * B_SZ * G4];                // [t][b][g]
__device__ float d_gx1[(size_t)T_LEN * B_SZ * G4];                // [t][b][g]
__device__ float d_h1T[(size_t)(T_LEN + 1) * HID * B_SZ];         // [t+1][k][b]
__device__ float d_h2T[(size_t)(T_LEN + 1) * HID * B_SZ];         // [t+1][k][b]

// Two-level barrier state. All counters MONOTONIC (mask checks, no resets)
// => deterministic under graph replay. 16 leaf counters, 256B apart
// (distinct L2 lines & safe from the bit-7 pair-collision) so the atomic
// ALU serialization is 16-way parallel instead of 256-deep on one line.
__device__ unsigned g_leaf[16 * 64];     // stride 64 uints = 256B
__device__ unsigned g_root = 0;
__device__ volatile unsigned g_gen = 0;

// ---------------------------------------------------------------------------
// Software grid barrier for NCTA=256 co-resident CTAs (2/SM).
// Arrival: 16 CTAs -> leaf counter (16 leaves in parallel, ~16*27 cyc),
// 16 leaf-leaders -> root (~16*27 cyc), last root arriver bumps g_gen.
// Spin on g_gen (read-only L2 broadcast). A spinner can never miss a
// generation: g_gen can only advance again after THIS CTA arrives again.
// ---------------------------------------------------------------------------
__device__ __forceinline__ void grid_sync() {
    __syncthreads();
    if (threadIdx.x == 0) {
        unsigned my = g_gen;                         // read BEFORE arriving
        __threadfence();                             // publish h stores
        bool released = false;
        if ((atomicAdd(&g_leaf[(blockIdx.x >> 4) * 64], 1u) & 15u) == 15u) {
            if ((atomicAdd(&g_root, 1u) & 15u) == 15u) {
                __threadfence();
                g_gen = my + 1;                      // release
                released = true;
            }
        }
        if (!released) while (g_gen == my) { }       // volatile spin
    }
    __syncthreads();
}

// fast, safe pointwise helpers (fp32, err ~1e-7; clamps avoid inf/NaN paths)
__device__ __forceinline__ float sigm(float x) {
    x = fminf(fmaxf(x, -30.f), 30.f);
    return __fdividef(1.f, 1.f + __expf(-x));
}
__device__ __forceinline__ float tanh_f(float x) {
    x = fminf(fmaxf(x, -15.f), 15.f);
    float e = __expf(-2.f * x);
    return (1.f - e) * __fdividef(1.f, 1.f + e);
}

// ---------------------------------------------------------------------------
// K0: zero the t=0 slabs of both hidden-state buffers.
// ---------------------------------------------------------------------------
__global__ void zero_h0_kernel() {
    int i = blockIdx.x * blockDim.x + threadIdx.x;
    if (i < HID * B_SZ) { d_h1T[i] = 0.f; d_h2T[i] = 0.f; }
}

// ---------------------------------------------------------------------------
// K1: gctx[b][g] = (b_ih0+b_hh0)[g] + ctxvec[b] . W_ih0[g][0:792]
// ---------------------------------------------------------------------------
__global__ __launch_bounds__(256) void gctx_kernel(
    const float* __restrict__ conv,      // [64][512]
    const int*   __restrict__ cat,       // [64][3]
    const float* __restrict__ num,       // [64][16]
    const float* __restrict__ ce0,       // [10][50]
    const float* __restrict__ ce1,       // [128][64]
    const float* __restrict__ ce2,       // [300][150]
    const float* __restrict__ W_ih0,     // [2048][1048]
    const float* __restrict__ b_ih0,
    const float* __restrict__ b_hh0)
{
    __shared__ __align__(16) float ctx[CTXD];
    int b = blockIdx.x, tid = threadIdx.x;
    int i0 = cat[b * 3 + 0], i1 = cat[b * 3 + 1], i2 = cat[b * 3 + 2];
    for (int i = tid; i < 512; i += 256) ctx[i]       = conv[b * 512 + i];
    for (int i = tid; i < 50;  i += 256) ctx[512 + i] = ce0[i0 * 50 + i];
    for (int i = tid; i < 64;  i += 256) ctx[562 + i] = ce1[i1 * 64 + i];
    for (int i = tid; i < 150; i += 256) ctx[626 + i] = ce2[i2 * 150 + i];
    for (int i = tid; i < 16;  i += 256) ctx[776 + i] = num[b * 16 + i];
    __syncthreads();

    const float4* cv = (const float4*)ctx;           // 198 float4s
    for (int g = tid; g < G4; g += 256) {
        const float4* wr = (const float4*)(W_ih0 + (size_t)g * INDIM);
        float acc = b_ih0[g] + b_hh0[g];
        #pragma unroll 4
        for (int kk = 0; kk < 198; ++kk) {
            float4 w = wr[kk], c4 = cv[kk];
            acc = fmaf(w.x, c4.x, fmaf(w.y, c4.y, fmaf(w.z, c4.z, fmaf(w.w, c4.w, acc))));
        }
        d_gctx[b * G4 + g] = acc;
    }
}

// ---------------------------------------------------------------------------
// K2: byte projection table P[(v*8+j)][g] = byte_emb[v] . W_ih0[g][792+32j : +32]
// ---------------------------------------------------------------------------
__global__ __launch_bounds__(256) void ptable_kernel(
    const float* __restrict__ byte_emb,  // [260][32]
    const float* __restrict__ W_ih0)
{
    int pid = blockIdx.x;                // v*8 + j
    int v = pid >> 3, j = pid & 7;
    __shared__ float e[32];
    if (threadIdx.x < 32) e[threadIdx.x] = byte_emb[v * 32 + threadIdx.x];
    __syncthreads();
    for (int g = threadIdx.x; g < G4; g += 256) {
        const float* wr = W_ih0 + (size_t)g * INDIM + CTXD + j * 32;
        float acc = 0.f;
        #pragma unroll
        for (int d = 0; d < 32; ++d) acc = fmaf(e[d], wr[d], acc);
        d_P[(size_t)pid * G4 + g] = acc;
    }
}

// ---------------------------------------------------------------------------
// K3: gx0[t][b][g] = gctx[b][g] + sum_j P[pad(b,t+j)*8+j][g]
// ---------------------------------------------------------------------------
__global__ __launch_bounds__(128) void gx0_kernel(
    const int* __restrict__ payload)     // [64][512]
{
    int t = blockIdx.x, b = blockIdx.y, tid = threadIdx.x;
    __shared__ int rows[8];
    if (tid < 8) {
        int q = t + tid;
        int v = (q < 7) ? 256 : ((q == 7) ? 257 : payload[b * 512 + (q - 8)]);
        rows[tid] = v * 8 + tid;
    }
    __syncthreads();
    float4* outp = (float4*)(d_gx0 + ((size_t)t * B_SZ + b) * G4);
    const float4* gc = (const float4*)(d_gctx + b * G4);
    #pragma unroll
    for (int p = 0; p < 4; ++p) {
        int g4 = p * 128 + tid;          // float4 index, 0..511
        float4 acc = gc[g4];
        #pragma unroll
        for (int j = 0; j < 8; ++j) {
            float4 pv = ((const float4*)(d_P + (size_t)rows[j] * G4))[g4];
            acc.x += pv.x; acc.y += pv.y; acc.z += pv.z; acc.w += pv.w;
        }
        outp[g4] = acc;
    }
}

// ---------------------------------------------------------------------------
// K4/K6: persistent LSTM recurrence, software-pipelined (R7-proven).
// 256 CTAs x 256 threads (2/SM). CTA owns 2 hidden units.
// Thread (p = tid&31 -> batch pair (2p,2p+1), rg = (tid>>5)&1 -> unit,
// ks = tid>>6 -> K-quarter of 128 k). Per k: 1 coalesced LDG.64 (h pair) +
// 1 broadcast LDS.128 (4 gate weights) + 8 scalar FMA; 16-deep explicit
// prefetch keeps ~4KB/warp in flight so memory streams at FMA pace.
// K-split partials combined via smem; ks==0 does pointwise for 2 batches.
// ---------------------------------------------------------------------------
__global__ __launch_bounds__(256, 2) void rec_kernel(
    const float* __restrict__ Whh,       // [2048][512]
    int layer)
{
    const float* gx = layer ? d_gx1 : d_gx0;
    float*       hT = layer ? d_h2T : d_h1T;

    __shared__ __align__(16) float Wk[HID][2][4];     // [k][unit][gate] 16 KB
    __shared__ __align__(16) float Red[3][2][32][8];  // [ks-1][unit][pair][2b*4g] 6 KB

    int tid = threadIdx.x;
    int u0 = blockIdx.x * 2;
    for (int idx = tid; idx < HID * 8; idx += 256) {
        int k = idx >> 3, rg_ = (idx >> 2) & 1, g = idx & 3;
        Wk[k][rg_][g] = Whh[((size_t)g * HID + u0 + rg_) * HID + k];
    }
    // (first grid_sync's __syncthreads orders Wk before use)

    int p  = tid & 31;          // batch pair index: b = 2p, 2p+1
    int rg = (tid >> 5) & 1;    // unit within CTA (uniform per warp)
    int ks = tid >> 6;          // K quarter (uniform per warp)
    int unit = u0 + rg;
    int kbase = ks * 128;

    float c0 = 0.f, c1 = 0.f;   // cell states for the 2 batches

#define REC_CHUNK(CH)                                                         \
    _Pragma("unroll")                                                         \
    for (int j = 0; j < 16; ++j) {                                            \
        float4 w = *(const float4*)&Wk[kbase + (CH) * 16 + j][rg][0];         \
        float2 hv = hb[j];                                                    \
        aI0 = fmaf(hv.x, w.x, aI0); aI1 = fmaf(hv.y, w.x, aI1);               \
        aF0 = fmaf(hv.x, w.y, aF0); aF1 = fmaf(hv.y, w.y, aF1);               \
        aG0 = fmaf(hv.x, w.z, aG0); aG1 = fmaf(hv.y, w.z, aG1);               \
        aO0 = fmaf(hv.x, w.w, aO0); aO1 = fmaf(hv.y, w.w, aO1);               \
    }

    for (int t = 0; t < T_LEN; ++t) {
        grid_sync();                                 // h[t] fully published
        const float2* hp2 =
            (const float2*)(hT + (size_t)t * (HID * B_SZ) + (size_t)kbase * 64) + p;

        // gate-input prefetch (consumed only at loop end)
        float q[8];
        if (ks == 0) {
            const float* g0 = gx + ((size_t)t * B_SZ + 2 * p) * G4 + unit;
            #pragma unroll
            for (int g = 0; g < 4; ++g) { q[g] = g0[g * 512]; q[4 + g] = g0[G4 + g * 512]; }
        }

        float aI0=0.f,aF0=0.f,aG0=0.f,aO0=0.f, aI1=0.f,aF1=0.f,aG1=0.f,aO1=0.f;

        float2 hb[16];
        #pragma unroll
        for (int j = 0; j < 16; ++j) hb[j] = hp2[j * 32];     // chunk 0

        #pragma unroll
        for (int ch = 0; ch < 7; ++ch) {
            float2 hn[16];
            #pragma unroll
            for (int j = 0; j < 16; ++j) hn[j] = hp2[((ch + 1) * 16 + j) * 32];
            REC_CHUNK(ch)
            #pragma unroll
            for (int j = 0; j < 16; ++j) hb[j] = hn[j];
        }
        REC_CHUNK(7)

        if (ks != 0) {
            float* r = &Red[ks - 1][rg][p][0];
            *(float4*)r       = make_float4(aI0, aF0, aG0, aO0);
            *(float4*)(r + 4) = make_float4(aI1, aF1, aG1, aO1);
        }
        __syncthreads();
        if (ks == 0) {
            #pragma unroll
            for (int s = 0; s < 3; ++s) {
                const float* r = &Red[s][rg][p][0];
                aI0 += r[0]; aF0 += r[1]; aG0 += r[2]; aO0 += r[3];
                aI1 += r[4]; aF1 += r[5]; aG1 += r[6]; aO1 += r[7];
            }
            float gi0 = aI0 + q[0], gf0 = aF0 + q[1], gg0 = aG0 + q[2], go0 = aO0 + q[3];
            float gi1 = aI1 + q[4], gf1 = aF1 + q[5], gg1 = aG1 + q[6], go1 = aO1 + q[7];
            c0 = fmaf(sigm(gf0), c0, sigm(gi0) * tanh_f(gg0));
            c1 = fmaf(sigm(gf1), c1, sigm(gi1) * tanh_f(gg1));
            float2 hout = make_float2(sigm(go0) * tanh_f(c0), sigm(go1) * tanh_f(c1));
            *((float2*)(hT + (size_t)(t + 1) * (HID * B_SZ) + (size_t)unit * 64) + p) = hout;
        }
    }
#undef REC_CHUNK
}

// ---------------------------------------------------------------------------
// K5: gx1[t][b][n] = h1[t][:][b] . W_ih1[n][:] + (b_ih1+b_hh1)[n]
// ---------------------------------------------------------------------------
__global__ __launch_bounds__(256) void gemm_gx1_kernel(
    const float* __restrict__ W,         // W_ih1 [2048][512]
    const float* __restrict__ bi,
    const float* __restrict__ bh)
{
    int n0 = blockIdx.x * 64;
    int t  = blockIdx.y;
    __shared__ __align__(16) float As[16][64];
    __shared__ __align__(16) float Bs[16][68];
    int tid = threadIdx.x;
    int tx = tid & 15, ty = tid >> 4;                // tx->n (coalesced writes)
    int lb = tid & 63, lk = tid >> 6;
    int bk = tid & 15, bn = tid >> 4;
    const float* Ap = d_h1T + (size_t)(t + 1) * (HID * B_SZ);
    float acc[4][4] = {};

    for (int kc = 0; kc < HID; kc += 16) {
        #pragma unroll
        for (int i = 0; i < 4; ++i)
            As[lk + 4 * i][lb] = Ap[(size_t)(kc + lk + 4 * i) * 64 + lb];
        #pragma unroll
        for (int i = 0; i < 4; ++i)
            Bs[bk][bn + 16 * i] = W[(size_t)(n0 + bn + 16 * i) * HID + kc + bk];
        __syncthreads();
        #pragma unroll
        for (int ku = 0; ku < 16; ++ku) {
            float4 av = *(const float4*)&As[ku][ty * 4];
            float4 bv = *(const float4*)&Bs[ku][tx * 4];
            acc[0][0] = fmaf(av.x, bv.x, acc[0][0]); acc[0][1] = fmaf(av.x, bv.y, acc[0][1]);
            acc[0][2] = fmaf(av.x, bv.z, acc[0][2]); acc[0][3] = fmaf(av.x, bv.w, acc[0][3]);
            acc[1][0] = fmaf(av.y, bv.x, acc[1][0]); acc[1][1] = fmaf(av.y, bv.y, acc[1][1]);
            acc[1][2] = fmaf(av.y, bv.z, acc[1][2]); acc[1][3] = fmaf(av.y, bv.w, acc[1][3]);
            acc[2][0] = fmaf(av.z, bv.x, acc[2][0]); acc[2][1] = fmaf(av.z, bv.y, acc[2][1]);
            acc[2][2] = fmaf(av.z, bv.z, acc[2][2]); acc[2][3] = fmaf(av.z, bv.w, acc[2][3]);
            acc[3][0] = fmaf(av.w, bv.x, acc[3][0]); acc[3][1] = fmaf(av.w, bv.y, acc[3][1]);
            acc[3][2] = fmaf(av.w, bv.z, acc[3][2]); acc[3][3] = fmaf(av.w, bv.w, acc[3][3]);
        }
        __syncthreads();
    }
    float bz[4];
    #pragma unroll
    for (int j = 0; j < 4; ++j) bz[j] = bi[n0 + tx * 4 + j] + bh[n0 + tx * 4 + j];
    #pragma unroll
    for (int i = 0; i < 4; ++i) {
        int b = ty * 4 + i;
        float4 st = make_float4(acc[i][0] + bz[0], acc[i][1] + bz[1],
                                acc[i][2] + bz[2], acc[i][3] + bz[3]);
        *(float4*)(d_gx1 + ((size_t)t * B_SZ + b) * G4 + n0 + tx * 4) = st;
    }
}

// ---------------------------------------------------------------------------
// K7: logits[b][t][v] = h2[t][:][b] . W_out[v][:] + b_out[v]
// ---------------------------------------------------------------------------
__global__ __launch_bounds__(256) void logits_kernel(
    const float* __restrict__ W,         // W_out [256][512]
    const float* __restrict__ bo,
    float* __restrict__ out)             // [64][512][256]
{
    int n0 = blockIdx.x * 64;
    int t  = blockIdx.y;
    __shared__ __align__(16) float As[16][64];
    __shared__ __align__(16) float Bs[16][68];
    int tid = threadIdx.x;
    int tx = tid & 15, ty = tid >> 4;
    int lb = tid & 63, lk = tid >> 6;
    int bk = tid & 15, bn = tid >> 4;
    const float* Ap = d_h2T + (size_t)(t + 1) * (HID * B_SZ);
    float acc[4][4] = {};

    for (int kc = 0; kc < HID; kc += 16) {
        #pragma unroll
        for (int i = 0; i < 4; ++i)
            As[lk + 4 * i][lb] = Ap[(size_t)(kc + lk + 4 * i) * 64 + lb];
        #pragma unroll
        for (int i = 0; i < 4; ++i)
            Bs[bk][bn + 16 * i] = W[(size_t)(n0 + bn + 16 * i) * HID + kc + bk];
        __syncthreads();
        #pragma unroll
        for (int ku = 0; ku < 16; ++ku) {
            float4 av = *(const float4*)&As[ku][ty * 4];
            float4 bv = *(const float4*)&Bs[ku][tx * 4];
            acc[0][0] = fmaf(av.x, bv.x, acc[0][0]); acc[0][1] = fmaf(av.x, bv.y, acc[0][1]);
            acc[0][2] = fmaf(av.x, bv.z, acc[0][2]); acc[0][3] = fmaf(av.x, bv.w, acc[0][3]);
            acc[1][0] = fmaf(av.y, bv.x, acc[1][0]); acc[1][1] = fmaf(av.y, bv.y, acc[1][1]);
            acc[1][2] = fmaf(av.y, bv.z, acc[1][2]); acc[1][3] = fmaf(av.y, bv.w, acc[1][3]);
            acc[2][0] = fmaf(av.z, bv.x, acc[2][0]); acc[2][1] = fmaf(av.z, bv.y, acc[2][1]);
            acc[2][2] = fmaf(av.z, bv.z, acc[2][2]); acc[2][3] = fmaf(av.z, bv.w, acc[2][3]);
            acc[3][0] = fmaf(av.w, bv.x, acc[3][0]); acc[3][1] = fmaf(av.w, bv.y, acc[3][1]);
            acc[3][2] = fmaf(av.w, bv.z, acc[3][2]); acc[3][3] = fmaf(av.w, bv.w, acc[3][3]);
        }
        __syncthreads();
    }
    float bz[4];
    #pragma unroll
    for (int j = 0; j < 4; ++j) bz[j] = bo[n0 + tx * 4 + j];
    #pragma unroll
    for (int i = 0; i < 4; ++i) {
        int b = ty * 4 + i;
        float4 st = make_float4(acc[i][0] + bz[0], acc[i][1] + bz[1],
                                acc[i][2] + bz[2], acc[i][3] + bz[3]);
        *(float4*)(out + ((size_t)b * T_LEN + t) * 256 + n0 + tx * 4) = st;
    }
}

// ---------------------------------------------------------------------------
// kernel_launch
// ---------------------------------------------------------------------------
extern "C" void kernel_launch(void* const* d_in, const int* in_sizes, int n_in,
                              void* d_out, int out_size) {
    const float* ecc     = (const float*)d_in[0];   // [64,512]
    const int*   cat     = (const int*)  d_in[1];   // [64,3]
    const float* num     = (const float*)d_in[2];   // [64,16]
    const int*   payload = (const int*)  d_in[3];   // [64,512]
    const float* ce0     = (const float*)d_in[4];
    const float* ce1     = (const float*)d_in[5];
    const float* ce2     = (const float*)d_in[6];
    const float* bemb    = (const float*)d_in[7];
    const float* W_ih0   = (const float*)d_in[8];
    const float* W_hh0   = (const float*)d_in[9];
    const float* b_ih0   = (const float*)d_in[10];
    const float* b_hh0   = (const float*)d_in[11];
    const float* W_ih1   = (const float*)d_in[12];
    const float* W_hh1   = (const float*)d_in[13];
    const float* b_ih1   = (const float*)d_in[14];
    const float* b_hh1   = (const float*)d_in[15];
    const float* W_outp  = (const float*)d_in[16];
    const float* b_outp  = (const float*)d_in[17];
    float* out = (float*)d_out;

    zero_h0_kernel<<<64, 512>>>();
    gctx_kernel<<<64, 256>>>(ecc, cat, num, ce0, ce1, ce2, W_ih0, b_ih0, b_hh0);
    ptable_kernel<<<2080, 256>>>(bemb, W_ih0);
    gx0_kernel<<<dim3(T_LEN, B_SZ), 128>>>(payload);
    rec_kernel<<<NCTA, 256>>>(W_hh0, 0);
    gemm_gx1_kernel<<<dim3(32, T_LEN), 256>>>(W_ih1, b_ih1, b_hh1);
    rec_kernel<<<NCTA, 256>>>(W_hh1, 1);
    logits_kernel<<<dim3(4, T_LEN), 256>>>(W_outp, b_outp, out);
}

// round 12
// speedup vs baseline: 1.1315x; 1.1315x over previous
#include <cuda_runtime.h>
#include <cuda_bf16.h>
#include <math.h>
#include <stdint.h>

// ---------------------------------------------------------------------------
// Problem constants
// ---------------------------------------------------------------------------
#define T_LEN 512
#define B_SZ  64
#define HID   512
#define G4    2048          // 4*HID (gate rows)
#define CTXD  792
#define INDIM 1048
#define NCTA  256           // persistent recurrence CTAs (2 units each, 2/SM)

// ---------------------------------------------------------------------------
// Device scratch
// ---------------------------------------------------------------------------
__device__ float d_gctx[B_SZ * G4];                               // [b][g]
__device__ float d_P[260 * 8 * G4];                               // [(v*8+j)][g]
__device__ float d_gx0[(size_t)T_LEN * B_SZ * G4];                // [t][b][g]
__device__ float d_gx1[(size_t)T_LEN * B_SZ * G4];                // [t][b][g]
__device__ float d_h1T[(size_t)(T_LEN + 1) * HID * B_SZ];         // [t+1][k][b]
__device__ float d_h2T[(size_t)(T_LEN + 1) * HID * B_SZ];         // [t+1][k][b]

// bf16-split operand buffers for tensor-core GEMMs
__device__ __nv_bfloat16 d_Ahi[(size_t)256 * 128 * 512];          // [tpair][row][k]
__device__ __nv_bfloat16 d_Alo[(size_t)256 * 128 * 512];
__device__ __nv_bfloat16 d_W1hi[2048 * 512], d_W1lo[2048 * 512];  // W_ih1
__device__ __nv_bfloat16 d_Wohi[256 * 512],  d_Wolo[256 * 512];   // W_out

__device__ unsigned g_cnt = 0;
__device__ volatile unsigned g_gen = 0;

// ---------------------------------------------------------------------------
// Software grid barrier (R7-proven single-counter form)
// ---------------------------------------------------------------------------
__device__ __forceinline__ void grid_sync() {
    __syncthreads();
    if (threadIdx.x == 0) {
        __threadfence();
        unsigned my = g_gen;                     // read BEFORE arriving
        if (atomicAdd(&g_cnt, 1u) == NCTA - 1) {
            g_cnt = 0;
            __threadfence();
            g_gen = my + 1;                      // release
        } else {
            while (g_gen == my) { }              // volatile spin (L2)
        }
    }
    __syncthreads();
}

// fast, safe pointwise helpers
__device__ __forceinline__ float sigm(float x) {
    x = fminf(fmaxf(x, -30.f), 30.f);
    return __fdividef(1.f, 1.f + __expf(-x));
}
__device__ __forceinline__ float tanh_f(float x) {
    x = fminf(fmaxf(x, -15.f), 15.f);
    float e = __expf(-2.f * x);
    return (1.f - e) * __fdividef(1.f, 1.f + e);
}

// ---------------------------------------------------------------------------
// warp-level tensor-core helpers (base PTX ISA: works at compute_103)
// ---------------------------------------------------------------------------
__device__ __forceinline__ uint32_t smem_u32(const void* p) {
    uint32_t a;
    asm("{ .reg .u64 t; cvta.to.shared.u64 t, %1; cvt.u32.u64 %0, t; }" : "=r"(a) : "l"(p));
    return a;
}
__device__ __forceinline__ void ldm_x4(uint32_t* r, uint32_t addr) {
    asm volatile("ldmatrix.sync.aligned.m8n8.x4.shared.b16 {%0,%1,%2,%3}, [%4];"
        : "=r"(r[0]), "=r"(r[1]), "=r"(r[2]), "=r"(r[3]) : "r"(addr));
}
__device__ __forceinline__ void hmma(float* d, const uint32_t* a, const uint32_t* b) {
    asm volatile("mma.sync.aligned.m16n8k16.row.col.f32.bf16.bf16.f32 "
        "{%0,%1,%2,%3}, {%4,%5,%6,%7}, {%8,%9}, {%0,%1,%2,%3};"
        : "+f"(d[0]), "+f"(d[1]), "+f"(d[2]), "+f"(d[3])
        : "r"(a[0]), "r"(a[1]), "r"(a[2]), "r"(a[3]), "r"(b[0]), "r"(b[1]));
}
// smem tile geometry: rows of 32 bf16 (64B), 16B chunks swizzled so any 8
// consecutive rows at one k-chunk touch 8 distinct 16B bank groups.
__device__ __forceinline__ uint32_t swz_off(int row, int c16) {
    return (uint32_t)(row * 64 + ((c16 ^ ((row >> 1) & 3)) << 4));
}
// ldmatrix.x4 lane address for a 16x16 fragment at (row0, kk) in such a tile.
__device__ __forceinline__ uint32_t frag_addr(uint32_t sbase, int row0, int kk, int lane) {
    int row = row0 + (lane & 7) + ((lane >> 3) & 1) * 8;
    int c16 = (kk >> 3) + (lane >> 4);
    return sbase + swz_off(row, c16);
}

// ---------------------------------------------------------------------------
// K0: zero t=0 slabs
// ---------------------------------------------------------------------------
__global__ void zero_h0_kernel() {
    int i = blockIdx.x * blockDim.x + threadIdx.x;
    if (i < HID * B_SZ) { d_h1T[i] = 0.f; d_h2T[i] = 0.f; }
}

// ---------------------------------------------------------------------------
// K1: gctx
// ---------------------------------------------------------------------------
__global__ __launch_bounds__(256) void gctx_kernel(
    const float* __restrict__ conv, const int* __restrict__ cat,
    const float* __restrict__ num, const float* __restrict__ ce0,
    const float* __restrict__ ce1, const float* __restrict__ ce2,
    const float* __restrict__ W_ih0, const float* __restrict__ b_ih0,
    const float* __restrict__ b_hh0)
{
    __shared__ __align__(16) float ctx[CTXD];
    int b = blockIdx.x, tid = threadIdx.x;
    int i0 = cat[b * 3 + 0], i1 = cat[b * 3 + 1], i2 = cat[b * 3 + 2];
    for (int i = tid; i < 512; i += 256) ctx[i]       = conv[b * 512 + i];
    for (int i = tid; i < 50;  i += 256) ctx[512 + i] = ce0[i0 * 50 + i];
    for (int i = tid; i < 64;  i += 256) ctx[562 + i] = ce1[i1 * 64 + i];
    for (int i = tid; i < 150; i += 256) ctx[626 + i] = ce2[i2 * 150 + i];
    for (int i = tid; i < 16;  i += 256) ctx[776 + i] = num[b * 16 + i];
    __syncthreads();
    const float4* cv = (const float4*)ctx;
    for (int g = tid; g < G4; g += 256) {
        const float4* wr = (const float4*)(W_ih0 + (size_t)g * INDIM);
        float acc = b_ih0[g] + b_hh0[g];
        #pragma unroll 4
        for (int kk = 0; kk < 198; ++kk) {
            float4 w = wr[kk], c4 = cv[kk];
            acc = fmaf(w.x, c4.x, fmaf(w.y, c4.y, fmaf(w.z, c4.z, fmaf(w.w, c4.w, acc))));
        }
        d_gctx[b * G4 + g] = acc;
    }
}

// ---------------------------------------------------------------------------
// K2: byte projection table
// ---------------------------------------------------------------------------
__global__ __launch_bounds__(256) void ptable_kernel(
    const float* __restrict__ byte_emb, const float* __restrict__ W_ih0)
{
    int pid = blockIdx.x;
    int v = pid >> 3, j = pid & 7;
    __shared__ float e[32];
    if (threadIdx.x < 32) e[threadIdx.x] = byte_emb[v * 32 + threadIdx.x];
    __syncthreads();
    for (int g = threadIdx.x; g < G4; g += 256) {
        const float* wr = W_ih0 + (size_t)g * INDIM + CTXD + j * 32;
        float acc = 0.f;
        #pragma unroll
        for (int d = 0; d < 32; ++d) acc = fmaf(e[d], wr[d], acc);
        d_P[(size_t)pid * G4 + g] = acc;
    }
}

// ---------------------------------------------------------------------------
// K3: gx0 assembly via gathers
// ---------------------------------------------------------------------------
__global__ __launch_bounds__(128) void gx0_kernel(const int* __restrict__ payload)
{
    int t = blockIdx.x, b = blockIdx.y, tid = threadIdx.x;
    __shared__ int rows[8];
    if (tid < 8) {
        int q = t + tid;
        int v = (q < 7) ? 256 : ((q == 7) ? 257 : payload[b * 512 + (q - 8)]);
        rows[tid] = v * 8 + tid;
    }
    __syncthreads();
    float4* outp = (float4*)(d_gx0 + ((size_t)t * B_SZ + b) * G4);
    const float4* gc = (const float4*)(d_gctx + b * G4);
    #pragma unroll
    for (int p = 0; p < 4; ++p) {
        int g4 = p * 128 + tid;
        float4 acc = gc[g4];
        #pragma unroll
        for (int j = 0; j < 8; ++j) {
            float4 pv = ((const float4*)(d_P + (size_t)rows[j] * G4))[g4];
            acc.x += pv.x; acc.y += pv.y; acc.z += pv.z; acc.w += pv.w;
        }
        outp[g4] = acc;
    }
}

// ---------------------------------------------------------------------------
// K4/K6: persistent LSTM recurrence (R7-proven, unchanged)
// ---------------------------------------------------------------------------
__global__ __launch_bounds__(256, 2) void rec_kernel(
    const float* __restrict__ Whh, int layer)
{
    const float* gx = layer ? d_gx1 : d_gx0;
    float*       hT = layer ? d_h2T : d_h1T;

    __shared__ __align__(16) float Wk[HID][2][4];
    __shared__ __align__(16) float Red[3][2][32][8];

    int tid = threadIdx.x;
    int u0 = blockIdx.x * 2;
    for (int idx = tid; idx < HID * 8; idx += 256) {
        int k = idx >> 3, rg_ = (idx >> 2) & 1, g = idx & 3;
        Wk[k][rg_][g] = Whh[((size_t)g * HID + u0 + rg_) * HID + k];
    }

    int p  = tid & 31;
    int rg = (tid >> 5) & 1;
    int ks = tid >> 6;
    int unit = u0 + rg;
    int kbase = ks * 128;

    float c0 = 0.f, c1 = 0.f;

#define REC_CHUNK(CH)                                                         \
    _Pragma("unroll")                                                         \
    for (int j = 0; j < 16; ++j) {                                            \
        float4 w = *(const float4*)&Wk[kbase + (CH) * 16 + j][rg][0];         \
        float2 hv = hb[j];                                                    \
        aI0 = fmaf(hv.x, w.x, aI0); aI1 = fmaf(hv.y, w.x, aI1);               \
        aF0 = fmaf(hv.x, w.y, aF0); aF1 = fmaf(hv.y, w.y, aF1);               \
        aG0 = fmaf(hv.x, w.z, aG0); aG1 = fmaf(hv.y, w.z, aG1);               \
        aO0 = fmaf(hv.x, w.w, aO0); aO1 = fmaf(hv.y, w.w, aO1);               \
    }

    for (int t = 0; t < T_LEN; ++t) {
        grid_sync();
        const float2* hp2 =
            (const float2*)(hT + (size_t)t * (HID * B_SZ) + (size_t)kbase * 64) + p;

        float q[8];
        if (ks == 0) {
            const float* g0 = gx + ((size_t)t * B_SZ + 2 * p) * G4 + unit;
            #pragma unroll
            for (int g = 0; g < 4; ++g) { q[g] = g0[g * 512]; q[4 + g] = g0[G4 + g * 512]; }
        }

        float aI0=0.f,aF0=0.f,aG0=0.f,aO0=0.f, aI1=0.f,aF1=0.f,aG1=0.f,aO1=0.f;

        float2 hb[16];
        #pragma unroll
        for (int j = 0; j < 16; ++j) hb[j] = hp2[j * 32];

        #pragma unroll
        for (int ch = 0; ch < 7; ++ch) {
            float2 hn[16];
            #pragma unroll
            for (int j = 0; j < 16; ++j) hn[j] = hp2[((ch + 1) * 16 + j) * 32];
            REC_CHUNK(ch)
            #pragma unroll
            for (int j = 0; j < 16; ++j) hb[j] = hn[j];
        }
        REC_CHUNK(7)

        if (ks != 0) {
            float* r = &Red[ks - 1][rg][p][0];
            *(float4*)r       = make_float4(aI0, aF0, aG0, aO0);
            *(float4*)(r + 4) = make_float4(aI1, aF1, aG1, aO1);
        }
        __syncthreads();
        if (ks == 0) {
            #pragma unroll
            for (int s = 0; s < 3; ++s) {
                const float* r = &Red[s][rg][p][0];
                aI0 += r[0]; aF0 += r[1]; aG0 += r[2]; aO0 += r[3];
                aI1 += r[4]; aF1 += r[5]; aG1 += r[6]; aO1 += r[7];
            }
            float gi0 = aI0 + q[0], gf0 = aF0 + q[1], gg0 = aG0 + q[2], go0 = aO0 + q[3];
            float gi1 = aI1 + q[4], gf1 = aF1 + q[5], gg1 = aG1 + q[6], go1 = aO1 + q[7];
            c0 = fmaf(sigm(gf0), c0, sigm(gi0) * tanh_f(gg0));
            c1 = fmaf(sigm(gf1), c1, sigm(gi1) * tanh_f(gg1));
            float2 hout = make_float2(sigm(go0) * tanh_f(c0), sigm(go1) * tanh_f(c1));
            *((float2*)(hT + (size_t)(t + 1) * (HID * B_SZ) + (size_t)unit * 64) + p) = hout;
        }
    }
#undef REC_CHUNK
}

// ---------------------------------------------------------------------------
// KW: fp32 weights -> bf16 hi/lo split. which: 0 = W_ih1, 1 = W_out.
// ---------------------------------------------------------------------------
__global__ __launch_bounds__(256) void convw_kernel(
    const float* __restrict__ W, int which, int n)
{
    __nv_bfloat16* hi = which ? d_Wohi : d_W1hi;
    __nv_bfloat16* lo = which ? d_Wolo : d_W1lo;
    int i = blockIdx.x * 256 + threadIdx.x;
    if (i < n) {
        float x = W[i];
        __nv_bfloat16 h = __float2bfloat16(x);
        hi[i] = h;
        lo[i] = __float2bfloat16(x - __bfloat162float(h));
    }
}

// ---------------------------------------------------------------------------
// KH: hT [t+1][k][b] fp32 -> A [tpair][row=(t&1)*64+b][k] bf16 hi/lo.
// ---------------------------------------------------------------------------
__global__ __launch_bounds__(256) void convh_kernel(int layer)
{
    const float* hT = layer ? d_h2T : d_h1T;
    int t = blockIdx.x, tid = threadIdx.x;
    int tp = t >> 1, r0 = (t & 1) * 64;
    __shared__ float tile[64][65];
    for (int kc = 0; kc < 512; kc += 64) {
        for (int idx = tid; idx < 4096; idx += 256) {
            int k = idx >> 6, b = idx & 63;
            tile[k][b] = hT[(size_t)(t + 1) * (HID * B_SZ) + (size_t)(kc + k) * 64 + b];
        }
        __syncthreads();
        for (int idx = tid; idx < 1024; idx += 256) {
            int b = idx >> 4, j = idx & 15;
            float x0 = tile[4 * j + 0][b], x1 = tile[4 * j + 1][b];
            float x2 = tile[4 * j + 2][b], x3 = tile[4 * j + 3][b];
            __nv_bfloat16 h0 = __float2bfloat16(x0), h1 = __float2bfloat16(x1);
            __nv_bfloat16 h2 = __float2bfloat16(x2), h3 = __float2bfloat16(x3);
            __nv_bfloat16 l0 = __float2bfloat16(x0 - __bfloat162float(h0));
            __nv_bfloat16 l1 = __float2bfloat16(x1 - __bfloat162float(h1));
            __nv_bfloat16 l2 = __float2bfloat16(x2 - __bfloat162float(h2));
            __nv_bfloat16 l3 = __float2bfloat16(x3 - __bfloat162float(h3));
            uint2 vh, vl;
            vh.x = (uint32_t)__bfloat16_as_ushort(h0) | ((uint32_t)__bfloat16_as_ushort(h1) << 16);
            vh.y = (uint32_t)__bfloat16_as_ushort(h2) | ((uint32_t)__bfloat16_as_ushort(h3) << 16);
            vl.x = (uint32_t)__bfloat16_as_ushort(l0) | ((uint32_t)__bfloat16_as_ushort(l1) << 16);
            vl.y = (uint32_t)__bfloat16_as_ushort(l2) | ((uint32_t)__bfloat16_as_ushort(l3) << 16);
            size_t o = ((size_t)(tp * 128 + r0 + b) * 512 + kc + 4 * j);
            *(uint2*)(d_Ahi + o) = vh;
            *(uint2*)(d_Alo + o) = vl;
        }
        __syncthreads();
    }
}

// ---------------------------------------------------------------------------
// KG: warp-tiled bf16-split mma.sync GEMM.
// D[128 rows x 128 n] = (Ah+Al)[tp] . (Bh+Bl)^T  ~= AhBh + AhBl + AlBh, fp32 acc.
// Grid (ntiles, 256 tp). 8 warps: mw = wid&3 (32-row group), nw = wid>>2
// (64-col group); warp tile 32x32 x (2 n-groups)=32x64: 2 m16 x 8 n8 frags.
// mode 0: B = W_ih1, out = d_gx1[t][b][n] + bias1+bias2
// mode 1: B = W_out, out = outp[b][t][v] + bias1
// ---------------------------------------------------------------------------
__global__ __launch_bounds__(256) void mma_gemm_kernel(
    const float* __restrict__ bias1, const float* __restrict__ bias2,
    float* __restrict__ outp, int mode)
{
    __shared__ __align__(16) uint8_t sAh[8192], sAl[8192], sBh[8192], sBl[8192];

    int tid = threadIdx.x, lane = tid & 31, wid = tid >> 5;
    int mw = wid & 3, nw = wid >> 2;
    int n0 = blockIdx.x * 128, tp = blockIdx.y;

    uint32_t bAh = smem_u32(sAh), bAl = smem_u32(sAl);
    uint32_t bBh = smem_u32(sBh), bBl = smem_u32(sBl);

    const __nv_bfloat16* Ah = d_Ahi + (size_t)tp * 128 * 512;
    const __nv_bfloat16* Al = d_Alo + (size_t)tp * 128 * 512;
    const __nv_bfloat16* Bh = (mode ? d_Wohi : d_W1hi) + (size_t)n0 * 512;
    const __nv_bfloat16* Bl = (mode ? d_Wolo : d_W1lo) + (size_t)n0 * 512;

    float acc[2][8][4] = {};

    // task split for tile loads: idx = tid + 256*i -> (row, 16B-chunk)
    int r0t = tid >> 2,          c0t = tid & 3;
    int r1t = (tid + 256) >> 2,  c1t = tid & 3;      // (tid+256)&3 == tid&3
    uint32_t d0 = swz_off(r0t, c0t), d1 = swz_off(r1t, c1t);

    for (int kc = 0; kc < 512; kc += 32) {
        // issue global loads (overlaps with previous chunk's mma)
        uint4 vah0 = *(const uint4*)(Ah + (size_t)r0t * 512 + kc + c0t * 8);
        uint4 vah1 = *(const uint4*)(Ah + (size_t)r1t * 512 + kc + c1t * 8);
        uint4 val0 = *(const uint4*)(Al + (size_t)r0t * 512 + kc + c0t * 8);
        uint4 val1 = *(const uint4*)(Al + (size_t)r1t * 512 + kc + c1t * 8);
        uint4 vbh0 = *(const uint4*)(Bh + (size_t)r0t * 512 + kc + c0t * 8);
        uint4 vbh1 = *(const uint4*)(Bh + (size_t)r1t * 512 + kc + c1t * 8);
        uint4 vbl0 = *(const uint4*)(Bl + (size_t)r0t * 512 + kc + c0t * 8);
        uint4 vbl1 = *(const uint4*)(Bl + (size_t)r1t * 512 + kc + c1t * 8);

        __syncthreads();                 // previous chunk's mma done
        *(uint4*)(sAh + d0) = vah0;  *(uint4*)(sAh + d1) = vah1;
        *(uint4*)(sAl + d0) = val0;  *(uint4*)(sAl + d1) = val1;
        *(uint4*)(sBh + d0) = vbh0;  *(uint4*)(sBh + d1) = vbh1;
        *(uint4*)(sBl + d0) = vbl0;  *(uint4*)(sBl + d1) = vbl1;
        __syncthreads();                 // tiles ready

        #pragma unroll
        for (int kk = 0; kk < 32; kk += 16) {
            uint32_t aH[2][4], aL[2][4], bb[8][2];
            #pragma unroll
            for (int mt = 0; mt < 2; ++mt) {
                ldm_x4(aH[mt], frag_addr(bAh, mw * 32 + mt * 16, kk, lane));
                ldm_x4(aL[mt], frag_addr(bAl, mw * 32 + mt * 16, kk, lane));
            }
            #pragma unroll
            for (int q = 0; q < 4; ++q) {
                uint32_t r[4];
                ldm_x4(r, frag_addr(bBh, nw * 64 + q * 16, kk, lane));
                bb[2 * q][0] = r[0]; bb[2 * q][1] = r[2];
                bb[2 * q + 1][0] = r[1]; bb[2 * q + 1][1] = r[3];
            }
            #pragma unroll
            for (int mt = 0; mt < 2; ++mt)
                #pragma unroll
                for (int nt = 0; nt < 8; ++nt) {
                    hmma(acc[mt][nt], aH[mt], bb[nt]);
                    hmma(acc[mt][nt], aL[mt], bb[nt]);
                }
            #pragma unroll
            for (int q = 0; q < 4; ++q) {
                uint32_t r[4];
                ldm_x4(r, frag_addr(bBl, nw * 64 + q * 16, kk, lane));
                bb[2 * q][0] = r[0]; bb[2 * q][1] = r[2];
                bb[2 * q + 1][0] = r[1]; bb[2 * q + 1][1] = r[3];
            }
            #pragma unroll
            for (int mt = 0; mt < 2; ++mt)
                #pragma unroll
                for (int nt = 0; nt < 8; ++nt)
                    hmma(acc[mt][nt], aH[mt], bb[nt]);
        }
    }

    // epilogue: D fragment lane map: rows (lane>>2, +8), cols 2*(lane&3), +1
    int gr = lane >> 2, gc2 = (lane & 3) * 2;
    #pragma unroll
    for (int mt = 0; mt < 2; ++mt) {
        #pragma unroll
        for (int half = 0; half < 2; ++half) {
            int row = mw * 32 + mt * 16 + gr + half * 8;
            int t = tp * 2 + (row >> 6), b = row & 63;
            #pragma unroll
            for (int nt = 0; nt < 8; ++nt) {
                int col = n0 + nw * 64 + nt * 8 + gc2;
                float z0 = bias1[col], z1 = bias1[col + 1];
                if (mode == 0) { z0 += bias2[col]; z1 += bias2[col + 1]; }
                float2 st = make_float2(acc[mt][nt][half * 2 + 0] + z0,
                                        acc[mt][nt][half * 2 + 1] + z1);
                if (mode == 0)
                    *(float2*)(d_gx1 + ((size_t)t * B_SZ + b) * G4 + col) = st;
                else
                    *(float2*)(outp + ((size_t)b * T_LEN + t) * 256 + col) = st;
            }
        }
    }
}

// ---------------------------------------------------------------------------
// kernel_launch
// ---------------------------------------------------------------------------
extern "C" void kernel_launch(void* const* d_in, const int* in_sizes, int n_in,
                              void* d_out, int out_size) {
    const float* ecc     = (const float*)d_in[0];
    const int*   cat     = (const int*)  d_in[1];
    const float* num     = (const float*)d_in[2];
    const int*   payload = (const int*)  d_in[3];
    const float* ce0     = (const float*)d_in[4];
    const float* ce1     = (const float*)d_in[5];
    const float* ce2     = (const float*)d_in[6];
    const float* bemb    = (const float*)d_in[7];
    const float* W_ih0   = (const float*)d_in[8];
    const float* W_hh0   = (const float*)d_in[9];
    const float* b_ih0   = (const float*)d_in[10];
    const float* b_hh0   = (const float*)d_in[11];
    const float* W_ih1   = (const float*)d_in[12];
    const float* W_hh1   = (const float*)d_in[13];
    const float* b_ih1   = (const float*)d_in[14];
    const float* b_hh1   = (const float*)d_in[15];
    const float* W_outp  = (const float*)d_in[16];
    const float* b_outp  = (const float*)d_in[17];
    float* out = (float*)d_out;

    zero_h0_kernel<<<64, 512>>>();
    gctx_kernel<<<64, 256>>>(ecc, cat, num, ce0, ce1, ce2, W_ih0, b_ih0, b_hh0);
    ptable_kernel<<<2080, 256>>>(bemb, W_ih0);
    gx0_kernel<<<dim3(T_LEN, B_SZ), 128>>>(payload);
    convw_kernel<<<4096, 256>>>(W_ih1, 0, 2048 * 512);
    convw_kernel<<<512, 256>>>(W_outp, 1, 256 * 512);
    rec_kernel<<<NCTA, 256>>>(W_hh0, 0);
    convh_kernel<<<512, 256>>>(0);
    mma_gemm_kernel<<<dim3(16, 256), 256>>>(b_ih1, b_hh1, out, 0);
    rec_kernel<<<NCTA, 256>>>(W_hh1, 1);
    convh_kernel<<<512, 256>>>(1);
    mma_gemm_kernel<<<dim3(2, 256), 256>>>(b_outp, b_outp, out, 1);
}

// round 13
// speedup vs baseline: 1.5491x; 1.3691x over previous
#include <cuda_runtime.h>
#include <cuda_bf16.h>
#include <math.h>
#include <stdint.h>

// ---------------------------------------------------------------------------
// Problem constants
// ---------------------------------------------------------------------------
#define T_LEN 512
#define B_SZ  64
#define HID   512
#define G4    2048          // 4*HID (gate rows)
#define CTXD  792
#define INDIM 1048

// ---------------------------------------------------------------------------
// Device scratch
// ---------------------------------------------------------------------------
__device__ float d_gctx[B_SZ * G4];                               // [b][g]
__device__ float d_P[260 * 8 * G4];                               // [(v*8+j)][g]
__device__ float d_gx0[(size_t)T_LEN * B_SZ * G4];                // [t][b][g]
__device__ float d_gx1[(size_t)T_LEN * B_SZ * G4];                // [t][b][g]

// hidden state, bf16 hi/lo split, layout [t+1][b][k] (slab 0 = zeros).
// This is simultaneously the B operand of the recurrence MMA and the A
// operand of the gx1/logits GEMMs (rows = t-local*64 + b).
__device__ __nv_bfloat16 d_h1hi[(size_t)(T_LEN + 1) * B_SZ * HID];
__device__ __nv_bfloat16 d_h1lo[(size_t)(T_LEN + 1) * B_SZ * HID];
__device__ __nv_bfloat16 d_h2hi[(size_t)(T_LEN + 1) * B_SZ * HID];
__device__ __nv_bfloat16 d_h2lo[(size_t)(T_LEN + 1) * B_SZ * HID];

// bf16-split weights for the big GEMMs
__device__ __nv_bfloat16 d_W1hi[2048 * 512], d_W1lo[2048 * 512];  // W_ih1
__device__ __nv_bfloat16 d_Wohi[256 * 512],  d_Wolo[256 * 512];   // W_out

// per-CTA tiled W_hh images for the recurrence (16 rows x 512 k, smem-tile
// format, 16KB per CTA per half): [layer][cta][8192 bf16]
__device__ __nv_bfloat16 d_WThi[2 * 128 * 8192];
__device__ __nv_bfloat16 d_WTlo[2 * 128 * 8192];

__device__ unsigned g_cnt = 0;
__device__ volatile unsigned g_gen = 0;

// ---------------------------------------------------------------------------
// Software grid barrier for 128 co-resident CTAs (rec_tc)
// ---------------------------------------------------------------------------
__device__ __forceinline__ void grid_sync128() {
    __syncthreads();
    if (threadIdx.x == 0) {
        __threadfence();
        unsigned my = g_gen;                     // read BEFORE arriving
        if (atomicAdd(&g_cnt, 1u) == 127u) {
            g_cnt = 0;
            __threadfence();
            g_gen = my + 1;                      // release
        } else {
            while (g_gen == my) { }              // volatile spin (L2)
        }
    }
    __syncthreads();
}

// fast, safe pointwise helpers
__device__ __forceinline__ float sigm(float x) {
    x = fminf(fmaxf(x, -30.f), 30.f);
    return __fdividef(1.f, 1.f + __expf(-x));
}
__device__ __forceinline__ float tanh_f(float x) {
    x = fminf(fmaxf(x, -15.f), 15.f);
    float e = __expf(-2.f * x);
    return (1.f - e) * __fdividef(1.f, 1.f + e);
}

// ---------------------------------------------------------------------------
// warp-level tensor-core + cp.async helpers (base PTX ISA, compute_103-safe)
// ---------------------------------------------------------------------------
__device__ __forceinline__ uint32_t smem_u32(const void* p) {
    uint32_t a;
    asm("{ .reg .u64 t; cvta.to.shared.u64 t, %1; cvt.u32.u64 %0, t; }" : "=r"(a) : "l"(p));
    return a;
}
__device__ __forceinline__ void ldm_x4(uint32_t* r, uint32_t addr) {
    asm volatile("ldmatrix.sync.aligned.m8n8.x4.shared.b16 {%0,%1,%2,%3}, [%4];"
        : "=r"(r[0]), "=r"(r[1]), "=r"(r[2]), "=r"(r[3]) : "r"(addr));
}
__device__ __forceinline__ void hmma(float* d, const uint32_t* a, const uint32_t* b) {
    asm volatile("mma.sync.aligned.m16n8k16.row.col.f32.bf16.bf16.f32 "
        "{%0,%1,%2,%3}, {%4,%5,%6,%7}, {%8,%9}, {%0,%1,%2,%3};"
        : "+f"(d[0]), "+f"(d[1]), "+f"(d[2]), "+f"(d[3])
        : "r"(a[0]), "r"(a[1]), "r"(a[2]), "r"(a[3]), "r"(b[0]), "r"(b[1]));
}
#define CP_ASYNC16(dst, src) \
    asm volatile("cp.async.cg.shared.global [%0], [%1], 16;" :: "r"(dst), "l"(src) : "memory")
#define CP_COMMIT() asm volatile("cp.async.commit_group;" ::: "memory")
#define CP_WAIT(N)  asm volatile("cp.async.wait_group %0;" :: "n"(N) : "memory")

// smem tile geometry: rows of 32 bf16 (64B), 16B chunks swizzled so any 8
// consecutive rows at one k-chunk touch 8 distinct 16B bank groups.
__device__ __forceinline__ uint32_t swz_off(int row, int c16) {
    return (uint32_t)(row * 64 + ((c16 ^ ((row >> 1) & 3)) << 4));
}
// ldmatrix.x4 lane address for a 16x16 fragment at (row0, kk) in such a tile.
__device__ __forceinline__ uint32_t frag_addr(uint32_t sbase, int row0, int kk, int lane) {
    int row = row0 + (lane & 7) + ((lane >> 3) & 1) * 8;
    int c16 = (kk >> 3) + (lane >> 4);
    return sbase + swz_off(row, c16);
}

// ---------------------------------------------------------------------------
// K0: zero t=0 slabs of all hidden-state buffers
// ---------------------------------------------------------------------------
__global__ void zero_h0_kernel() {
    int i = blockIdx.x * blockDim.x + threadIdx.x;
    if (i < HID * B_SZ) {
        __nv_bfloat16 z = __float2bfloat16(0.f);
        d_h1hi[i] = z; d_h1lo[i] = z; d_h2hi[i] = z; d_h2lo[i] = z;
    }
}

// ---------------------------------------------------------------------------
// K1: gctx
// ---------------------------------------------------------------------------
__global__ __launch_bounds__(256) void gctx_kernel(
    const float* __restrict__ conv, const int* __restrict__ cat,
    const float* __restrict__ num, const float* __restrict__ ce0,
    const float* __restrict__ ce1, const float* __restrict__ ce2,
    const float* __restrict__ W_ih0, const float* __restrict__ b_ih0,
    const float* __restrict__ b_hh0)
{
    __shared__ __align__(16) float ctx[CTXD];
    int b = blockIdx.x, tid = threadIdx.x;
    int i0 = cat[b * 3 + 0], i1 = cat[b * 3 + 1], i2 = cat[b * 3 + 2];
    for (int i = tid; i < 512; i += 256) ctx[i]       = conv[b * 512 + i];
    for (int i = tid; i < 50;  i += 256) ctx[512 + i] = ce0[i0 * 50 + i];
    for (int i = tid; i < 64;  i += 256) ctx[562 + i] = ce1[i1 * 64 + i];
    for (int i = tid; i < 150; i += 256) ctx[626 + i] = ce2[i2 * 150 + i];
    for (int i = tid; i < 16;  i += 256) ctx[776 + i] = num[b * 16 + i];
    __syncthreads();
    const float4* cv = (const float4*)ctx;
    for (int g = tid; g < G4; g += 256) {
        const float4* wr = (const float4*)(W_ih0 + (size_t)g * INDIM);
        float acc = b_ih0[g] + b_hh0[g];
        #pragma unroll 4
        for (int kk = 0; kk < 198; ++kk) {
            float4 w = wr[kk], c4 = cv[kk];
            acc = fmaf(w.x, c4.x, fmaf(w.y, c4.y, fmaf(w.z, c4.z, fmaf(w.w, c4.w, acc))));
        }
        d_gctx[b * G4 + g] = acc;
    }
}

// ---------------------------------------------------------------------------
// K2: byte projection table
// ---------------------------------------------------------------------------
__global__ __launch_bounds__(256) void ptable_kernel(
    const float* __restrict__ byte_emb, const float* __restrict__ W_ih0)
{
    int pid = blockIdx.x;
    int v = pid >> 3, j = pid & 7;
    __shared__ float e[32];
    if (threadIdx.x < 32) e[threadIdx.x] = byte_emb[v * 32 + threadIdx.x];
    __syncthreads();
    for (int g = threadIdx.x; g < G4; g += 256) {
        const float* wr = W_ih0 + (size_t)g * INDIM + CTXD + j * 32;
        float acc = 0.f;
        #pragma unroll
        for (int d = 0; d < 32; ++d) acc = fmaf(e[d], wr[d], acc);
        d_P[(size_t)pid * G4 + g] = acc;
    }
}

// ---------------------------------------------------------------------------
// K3: gx0 assembly via gathers
// ---------------------------------------------------------------------------
__global__ __launch_bounds__(128) void gx0_kernel(const int* __restrict__ payload)
{
    int t = blockIdx.x, b = blockIdx.y, tid = threadIdx.x;
    __shared__ int rows[8];
    if (tid < 8) {
        int q = t + tid;
        int v = (q < 7) ? 256 : ((q == 7) ? 257 : payload[b * 512 + (q - 8)]);
        rows[tid] = v * 8 + tid;
    }
    __syncthreads();
    float4* outp = (float4*)(d_gx0 + ((size_t)t * B_SZ + b) * G4);
    const float4* gc = (const float4*)(d_gctx + b * G4);
    #pragma unroll
    for (int p = 0; p < 4; ++p) {
        int g4 = p * 128 + tid;
        float4 acc = gc[g4];
        #pragma unroll
        for (int j = 0; j < 8; ++j) {
            float4 pv = ((const float4*)(d_P + (size_t)rows[j] * G4))[g4];
            acc.x += pv.x; acc.y += pv.y; acc.z += pv.z; acc.w += pv.w;
        }
        outp[g4] = acc;
    }
}

// ---------------------------------------------------------------------------
// KW: fp32 weights -> bf16 hi/lo split (for mma GEMMs). which: 0=W_ih1, 1=W_out.
// ---------------------------------------------------------------------------
__global__ __launch_bounds__(256) void convw_kernel(
    const float* __restrict__ W, int which, int n)
{
    __nv_bfloat16* hi = which ? d_Wohi : d_W1hi;
    __nv_bfloat16* lo = which ? d_Wolo : d_W1lo;
    int i = blockIdx.x * 256 + threadIdx.x;
    if (i < n) {
        float x = W[i];
        __nv_bfloat16 h = __float2bfloat16(x);
        hi[i] = h;
        lo[i] = __float2bfloat16(x - __bfloat162float(h));
    }
}

// ---------------------------------------------------------------------------
// KWT: W_hh -> per-CTA tiled bf16 hi/lo images for rec_tc.
// CTA c owns rows r = g*4 + u  (g = gate 0..3 i/f/g/o, u = unit local 0..3),
// source row = g*512 + 4c + u. Tile image: 16 chunks of [16 rows][32 k],
// chunk stride 1KB, inner offset swz_off(r, c16).
// One thread handles one 16B group (8 k). 131072 groups per layer.
// ---------------------------------------------------------------------------
__global__ __launch_bounds__(256) void convwhh_kernel(
    const float* __restrict__ Whh, int layer)
{
    int idx = blockIdx.x * 256 + threadIdx.x;    // [0, 131072)
    int c = idx >> 10, rem = idx & 1023;
    int r = rem >> 6, rem2 = rem & 63;
    int ch = rem2 >> 2, c16 = rem2 & 3;
    int g = r >> 2, u = r & 3;
    const float* src = Whh + ((size_t)(g * 512 + c * 4 + u)) * 512 + ch * 32 + c16 * 8;
    float4 v0 = *(const float4*)src;
    float4 v1 = *(const float4*)(src + 4);
    float x[8] = {v0.x, v0.y, v0.z, v0.w, v1.x, v1.y, v1.z, v1.w};
    ushort hs[8], ls[8];
    #pragma unroll
    for (int i = 0; i < 8; ++i) {
        __nv_bfloat16 h = __float2bfloat16(x[i]);
        __nv_bfloat16 l = __float2bfloat16(x[i] - __bfloat162float(h));
        hs[i] = __bfloat16_as_ushort(h);
        ls[i] = __bfloat16_as_ushort(l);
    }
    size_t dst = ((size_t)layer * 128 + c) * 16384 + ch * 1024 + swz_off(r, c16);
    uint4 ph, pl;
    ph.x = hs[0] | ((uint32_t)hs[1] << 16); ph.y = hs[2] | ((uint32_t)hs[3] << 16);
    ph.z = hs[4] | ((uint32_t)hs[5] << 16); ph.w = hs[6] | ((uint32_t)hs[7] << 16);
    pl.x = ls[0] | ((uint32_t)ls[1] << 16); pl.y = ls[2] | ((uint32_t)ls[3] << 16);
    pl.z = ls[4] | ((uint32_t)ls[5] << 16); pl.w = ls[6] | ((uint32_t)ls[7] << 16);
    *(uint4*)((uint8_t*)d_WThi + dst) = ph;
    *(uint4*)((uint8_t*)d_WTlo + dst) = pl;
}

// ---------------------------------------------------------------------------
// K4/K6: tensor-core persistent LSTM recurrence.
// 128 CTAs x 128 threads (1/SM, 160KB smem). CTA owns 4 units (16 gate rows,
// stationary A tiles in smem). Per step: cp.async streams h[t] (bf16 hi/lo,
// [b][k]) into swizzled B tiles in 4 quarters overlapped with MMA; 4 warps x
// 2 n-tiles compute D[16 rows x 64 b] = 3-term bf16-split MMA; lanes<16 pair
// with lane+16 via shfl_xor(16) to assemble (i,f,g,o), do the pointwise in
// registers (c stays resident), and store h[t+1] as bf16 hi/lo.
// ---------------------------------------------------------------------------
__global__ __launch_bounds__(128, 1) void rec_tc_kernel(int layer)
{
    extern __shared__ __align__(16) uint8_t sm[];
    uint8_t* sAh = sm;                 // 16 KB
    uint8_t* sAl = sm + 16384;         // 16 KB
    uint8_t* sBh = sm + 32768;         // 64 KB: [16 ch][64 b][64B]
    uint8_t* sBl = sm + 98304;         // 64 KB

    const float* gx = layer ? d_gx1 : d_gx0;
    __nv_bfloat16* hhi = layer ? d_h2hi : d_h1hi;
    __nv_bfloat16* hlo = layer ? d_h2lo : d_h1lo;

    int tid = threadIdx.x, lane = tid & 31, w = tid >> 5;
    int blk = blockIdx.x;

    // stationary A tiles (already tile-formatted by convwhh)
    {
        const uint4* srcH = (const uint4*)(d_WThi + ((size_t)layer * 128 + blk) * 8192);
        const uint4* srcL = (const uint4*)(d_WTlo + ((size_t)layer * 128 + blk) * 8192);
        for (int i = tid; i < 1024; i += 128) {
            ((uint4*)sAh)[i] = srcH[i];
            ((uint4*)sAl)[i] = srcL[i];
        }
    }

    uint32_t bAh = smem_u32(sAh), bAl = smem_u32(sAl);
    uint32_t bBh = smem_u32(sBh), bBl = smem_u32(sBl);

    int r = lane >> 2;                 // D row group (0..7)
    int cp = lane & 3;                 // batch pair within n-tile
    bool pw = (r < 4);                 // pointwise-owning lanes (i,g rows)
    int uglob = blk * 4 + r;           // this lane's unit (when pw)

    float cst[2][2] = {};              // cell state [nt][batch 0/1]

    for (int t = 0; t < T_LEN; ++t) {
        grid_sync128();                // h[t] fully published by all CTAs
        const uint8_t* srcHi = (const uint8_t*)hhi + (size_t)t * 65536;
        const uint8_t* srcLo = (const uint8_t*)hlo + (size_t)t * 65536;

        // prefetch gate inputs (consumed in pointwise only)
        float q[2][4][2];
        if (pw) {
            #pragma unroll
            for (int nt = 0; nt < 2; ++nt) {
                int b0 = w * 16 + nt * 8 + cp * 2;
                const float* g0 = gx + ((size_t)t * B_SZ + b0) * G4 + uglob;
                #pragma unroll
                for (int g = 0; g < 4; ++g) {
                    q[nt][g][0] = g0[g * 512];
                    q[nt][g][1] = g0[g * 512 + G4];
                }
            }
        }

        // issue all B-tile cp.asyncs in 4 quarter-groups (chunks 4q..4q+4)
        #pragma unroll
        for (int qq = 0; qq < 4; ++qq) {
            #pragma unroll
            for (int i = 0; i < 8; ++i) {
                int idx = tid + i * 128;                 // [0,1024)
                int b = idx >> 4, chl = (idx >> 2) & 3, c16 = idx & 3;
                int ch = qq * 4 + chl;
                uint32_t so = (uint32_t)(b * 1024 + ch * 64 + c16 * 16);
                uint32_t dofs = ch * 4096 + swz_off(b, c16);
                CP_ASYNC16(bBh + dofs, srcHi + so);
                CP_ASYNC16(bBl + dofs, srcLo + so);
            }
            CP_COMMIT();
        }

        float acc[2][4] = {};

        // MMA quarters, overlapped with the remaining cp.async streams
        #pragma unroll
        for (int qq = 0; qq < 4; ++qq) {
            if (qq == 0) CP_WAIT(3);
            else if (qq == 1) CP_WAIT(2);
            else if (qq == 2) CP_WAIT(1);
            else CP_WAIT(0);
            __syncthreads();
            #pragma unroll
            for (int chl = 0; chl < 4; ++chl) {
                int ch = qq * 4 + chl;
                #pragma unroll
                for (int kk = 0; kk < 32; kk += 16) {
                    uint32_t aH[4], aL[4], rr[4];
                    ldm_x4(aH, frag_addr(bAh + ch * 1024, 0, kk, lane));
                    ldm_x4(aL, frag_addr(bAl + ch * 1024, 0, kk, lane));
                    uint32_t bH[2][2], bL[2][2];
                    ldm_x4(rr, frag_addr(bBh + ch * 4096, w * 16, kk, lane));
                    bH[0][0] = rr[0]; bH[0][1] = rr[2];
                    bH[1][0] = rr[1]; bH[1][1] = rr[3];
                    ldm_x4(rr, frag_addr(bBl + ch * 4096, w * 16, kk, lane));
                    bL[0][0] = rr[0]; bL[0][1] = rr[2];
                    bL[1][0] = rr[1]; bL[1][1] = rr[3];
                    #pragma unroll
                    for (int nt = 0; nt < 2; ++nt) {
                        hmma(acc[nt], aH, bH[nt]);
                        hmma(acc[nt], aH, bL[nt]);
                        hmma(acc[nt], aL, bH[nt]);
                    }
                }
            }
        }
        __syncthreads();   // B tiles free for next step's cp.async after this

        // pointwise: lanes<16 have i (acc[nt][0..1]) and g (acc[nt][2..3]);
        // partner lane+16 has f and o for the same unit/batches.
        #pragma unroll
        for (int nt = 0; nt < 2; ++nt) {
            float f0 = __shfl_xor_sync(0xffffffffu, acc[nt][0], 16);
            float f1 = __shfl_xor_sync(0xffffffffu, acc[nt][1], 16);
            float o0 = __shfl_xor_sync(0xffffffffu, acc[nt][2], 16);
            float o1 = __shfl_xor_sync(0xffffffffu, acc[nt][3], 16);
            if (pw) {
                float gi0 = acc[nt][0] + q[nt][0][0];
                float gf0 = f0          + q[nt][1][0];
                float gg0 = acc[nt][2] + q[nt][2][0];
                float go0 = o0          + q[nt][3][0];
                float gi1 = acc[nt][1] + q[nt][0][1];
                float gf1 = f1          + q[nt][1][1];
                float gg1 = acc[nt][3] + q[nt][2][1];
                float go1 = o1          + q[nt][3][1];
                cst[nt][0] = fmaf(sigm(gf0), cst[nt][0], sigm(gi0) * tanh_f(gg0));
                cst[nt][1] = fmaf(sigm(gf1), cst[nt][1], sigm(gi1) * tanh_f(gg1));
                float h0 = sigm(go0) * tanh_f(cst[nt][0]);
                float h1 = sigm(go1) * tanh_f(cst[nt][1]);
                int b0 = w * 16 + nt * 8 + cp * 2;
                size_t base = (size_t)(t + 1) * 32768 + (size_t)b0 * 512 + uglob;
                __nv_bfloat16 hh0 = __float2bfloat16(h0);
                __nv_bfloat16 hh1 = __float2bfloat16(h1);
                hhi[base]       = hh0;
                hlo[base]       = __float2bfloat16(h0 - __bfloat162float(hh0));
                hhi[base + 512] = hh1;
                hlo[base + 512] = __float2bfloat16(h1 - __bfloat162float(hh1));
            }
        }
    }
}

// ---------------------------------------------------------------------------
// KG: warp-tiled bf16-split mma.sync GEMM (R12-proven).
// A rows come straight from the h slabs (row = t_local*64 + b at slab 2tp+1).
// mode 0: A=h1, B=W_ih1, out = d_gx1 + bias1+bias2
// mode 1: A=h2, B=W_out, out = outp  + bias1
// ---------------------------------------------------------------------------
__global__ __launch_bounds__(256) void mma_gemm_kernel(
    const float* __restrict__ bias1, const float* __restrict__ bias2,
    float* __restrict__ outp, int mode)
{
    __shared__ __align__(16) uint8_t sAh[8192], sAl[8192], sBh[8192], sBl[8192];

    int tid = threadIdx.x, lane = tid & 31, wid = tid >> 5;
    int mw = wid & 3, nw = wid >> 2;
    int n0 = blockIdx.x * 128, tp = blockIdx.y;

    uint32_t bAh = smem_u32(sAh), bAl = smem_u32(sAl);
    uint32_t bBh = smem_u32(sBh), bBl = smem_u32(sBl);

    const __nv_bfloat16* Ah = (mode ? d_h2hi : d_h1hi) + (size_t)(2 * tp + 1) * 32768;
    const __nv_bfloat16* Al = (mode ? d_h2lo : d_h1lo) + (size_t)(2 * tp + 1) * 32768;
    const __nv_bfloat16* Bh = (mode ? d_Wohi : d_W1hi) + (size_t)n0 * 512;
    const __nv_bfloat16* Bl = (mode ? d_Wolo : d_W1lo) + (size_t)n0 * 512;

    float acc[2][8][4] = {};

    int r0t = tid >> 2,          c0t = tid & 3;
    int r1t = (tid + 256) >> 2,  c1t = tid & 3;
    uint32_t d0 = swz_off(r0t, c0t), d1 = swz_off(r1t, c1t);

    for (int kc = 0; kc < 512; kc += 32) {
        uint4 vah0 = *(const uint4*)(Ah + (size_t)r0t * 512 + kc + c0t * 8);
        uint4 vah1 = *(const uint4*)(Ah + (size_t)r1t * 512 + kc + c1t * 8);
        uint4 val0 = *(const uint4*)(Al + (size_t)r0t * 512 + kc + c0t * 8);
        uint4 val1 = *(const uint4*)(Al + (size_t)r1t * 512 + kc + c1t * 8);
        uint4 vbh0 = *(const uint4*)(Bh + (size_t)r0t * 512 + kc + c0t * 8);
        uint4 vbh1 = *(const uint4*)(Bh + (size_t)r1t * 512 + kc + c1t * 8);
        uint4 vbl0 = *(const uint4*)(Bl + (size_t)r0t * 512 + kc + c0t * 8);
        uint4 vbl1 = *(const uint4*)(Bl + (size_t)r1t * 512 + kc + c1t * 8);

        __syncthreads();
        *(uint4*)(sAh + d0) = vah0;  *(uint4*)(sAh + d1) = vah1;
        *(uint4*)(sAl + d0) = val0;  *(uint4*)(sAl + d1) = val1;
        *(uint4*)(sBh + d0) = vbh0;  *(uint4*)(sBh + d1) = vbh1;
        *(uint4*)(sBl + d0) = vbl0;  *(uint4*)(sBl + d1) = vbl1;
        __syncthreads();

        #pragma unroll
        for (int kk = 0; kk < 32; kk += 16) {
            uint32_t aH[2][4], aL[2][4], bb[8][2];
            #pragma unroll
            for (int mt = 0; mt < 2; ++mt) {
                ldm_x4(aH[mt], frag_addr(bAh, mw * 32 + mt * 16, kk, lane));
                ldm_x4(aL[mt], frag_addr(bAl, mw * 32 + mt * 16, kk, lane));
            }
            #pragma unroll
            for (int q = 0; q < 4; ++q) {
                uint32_t rr[4];
                ldm_x4(rr, frag_addr(bBh, nw * 64 + q * 16, kk, lane));
                bb[2 * q][0] = rr[0]; bb[2 * q][1] = rr[2];
                bb[2 * q + 1][0] = rr[1]; bb[2 * q + 1][1] = rr[3];
            }
            #pragma unroll
            for (int mt = 0; mt < 2; ++mt)
                #pragma unroll
                for (int nt = 0; nt < 8; ++nt) {
                    hmma(acc[mt][nt], aH[mt], bb[nt]);
                    hmma(acc[mt][nt], aL[mt], bb[nt]);
                }
            #pragma unroll
            for (int q = 0; q < 4; ++q) {
                uint32_t rr[4];
                ldm_x4(rr, frag_addr(bBl, nw * 64 + q * 16, kk, lane));
                bb[2 * q][0] = rr[0]; bb[2 * q][1] = rr[2];
                bb[2 * q + 1][0] = rr[1]; bb[2 * q + 1][1] = rr[3];
            }
            #pragma unroll
            for (int mt = 0; mt < 2; ++mt)
                #pragma unroll
                for (int nt = 0; nt < 8; ++nt)
                    hmma(acc[mt][nt], aH[mt], bb[nt]);
        }
    }

    int gr = lane >> 2, gc2 = (lane & 3) * 2;
    #pragma unroll
    for (int mt = 0; mt < 2; ++mt) {
        #pragma unroll
        for (int half = 0; half < 2; ++half) {
            int row = mw * 32 + mt * 16 + gr + half * 8;
            int t = tp * 2 + (row >> 6), b = row & 63;
            #pragma unroll
            for (int nt = 0; nt < 8; ++nt) {
                int col = n0 + nw * 64 + nt * 8 + gc2;
                float z0 = bias1[col], z1 = bias1[col + 1];
                if (mode == 0) { z0 += bias2[col]; z1 += bias2[col + 1]; }
                float2 st = make_float2(acc[mt][nt][half * 2 + 0] + z0,
                                        acc[mt][nt][half * 2 + 1] + z1);
                if (mode == 0)
                    *(float2*)(d_gx1 + ((size_t)t * B_SZ + b) * G4 + col) = st;
                else
                    *(float2*)(outp + ((size_t)b * T_LEN + t) * 256 + col) = st;
            }
        }
    }
}

// ---------------------------------------------------------------------------
// kernel_launch
// ---------------------------------------------------------------------------
extern "C" void kernel_launch(void* const* d_in, const int* in_sizes, int n_in,
                              void* d_out, int out_size) {
    const float* ecc     = (const float*)d_in[0];
    const int*   cat     = (const int*)  d_in[1];
    const float* num     = (const float*)d_in[2];
    const int*   payload = (const int*)  d_in[3];
    const float* ce0     = (const float*)d_in[4];
    const float* ce1     = (const float*)d_in[5];
    const float* ce2     = (const float*)d_in[6];
    const float* bemb    = (const float*)d_in[7];
    const float* W_ih0   = (const float*)d_in[8];
    const float* W_hh0   = (const float*)d_in[9];
    const float* b_ih0   = (const float*)d_in[10];
    const float* b_hh0   = (const float*)d_in[11];
    const float* W_ih1   = (const float*)d_in[12];
    const float* W_hh1   = (const float*)d_in[13];
    const float* b_ih1   = (const float*)d_in[14];
    const float* b_hh1   = (const float*)d_in[15];
    const float* W_outp  = (const float*)d_in[16];
    const float* b_outp  = (const float*)d_in[17];
    float* out = (float*)d_out;

    cudaFuncSetAttribute(rec_tc_kernel,
                         cudaFuncAttributeMaxDynamicSharedMemorySize, 163840);

    zero_h0_kernel<<<64, 512>>>();
    gctx_kernel<<<64, 256>>>(ecc, cat, num, ce0, ce1, ce2, W_ih0, b_ih0, b_hh0);
    ptable_kernel<<<2080, 256>>>(bemb, W_ih0);
    gx0_kernel<<<dim3(T_LEN, B_SZ), 128>>>(payload);
    convw_kernel<<<4096, 256>>>(W_ih1, 0, 2048 * 512);
    convw_kernel<<<512, 256>>>(W_outp, 1, 256 * 512);
    convwhh_kernel<<<512, 256>>>(W_hh0, 0);
    convwhh_kernel<<<512, 256>>>(W_hh1, 1);
    rec_tc_kernel<<<128, 128, 163840>>>(0);
    mma_gemm_kernel<<<dim3(16, 256), 256>>>(b_ih1, b_hh1, out, 0);
    rec_tc_kernel<<<128, 128, 163840>>>(1);
    mma_gemm_kernel<<<dim3(2, 256), 256>>>(b_outp, b_outp, out, 1);
}